// round 14
// baseline (speedup 1.0000x reference)
#include <cuda_runtime.h>
#include <cuda_bf16.h>
#include <cstdint>
#include <cstddef>

// ---------------------------------------------------------------------------
// QLSTM  T=512 B=64 D=512 H=512
//  z_t = x_t@Wx + b4 + h_t@(Wh+R)
//  Phase A (prep):   split X and weights into bf16 hi/lo, permute columns
//  Phase B (gemm):   Z0[32768,2048] = X@Wx + b4   (3-product bf16 split)
//  Phase C (rnn):    persistent, 128 CTAs = 4 batch-groups x 32 N-slices.
//                    CTA (g,s): batch rows [16g,16g+16), cols [64s,64s+64).
//                    R13 = R12 + (a) hi/lo chunked H gather with early GEMM
//                    start (2/3 of mma runs while A-lo arrives), (b) the
//                    pairwise partial exchange uses 64-thread named barriers
//                    instead of a CTA-wide __syncthreads.
//  Column permutation: z column for (hidden hc, gate g) stored at n = hc*4+g
// ---------------------------------------------------------------------------

#define TT 512
#define BB 64
#define DD 512
#define HH 512
#define NCOLS 2048
#define MTOT (TT * BB)          // 32768
#define RNN_CTAS 128

// ------------------------- static device scratch ---------------------------
__device__ __align__(128) __nv_bfloat16 g_Ax[(size_t)MTOT * 1024];   // X split  [m][hi|lo]
__device__ __align__(128) __nv_bfloat16 g_Bx[(size_t)NCOLS * 1024];  // Wx split [n][hi|lo]
__device__ __align__(128) __nv_bfloat16 g_Br[(size_t)NCOLS * 1024];  // (Wh+R)   [n][hi|lo]
__device__ __align__(128) float g_b4[NCOLS];
__device__ __align__(128) float g_Z0[(size_t)MTOT * NCOLS];          // 256 MB
__device__ __align__(128) __nv_bfloat16 g_hbuf[2 * BB * 1024];       // h split ping-pong
__device__ __align__(128) unsigned g_flags[RNN_CTAS * 32];           // 1 line / CTA

// ------------------------------ helpers ------------------------------------
__device__ __forceinline__ uint32_t smem_u32(const void* p) {
    return (uint32_t)__cvta_generic_to_shared(p);
}
__device__ __forceinline__ void ldsm_x4(uint32_t& r0, uint32_t& r1, uint32_t& r2,
                                        uint32_t& r3, uint32_t addr) {
    asm volatile("ldmatrix.sync.aligned.m8n8.x4.shared.b16 {%0,%1,%2,%3},[%4];\n"
                 : "=r"(r0), "=r"(r1), "=r"(r2), "=r"(r3) : "r"(addr));
}
__device__ __forceinline__ void ldsm_x2(uint32_t& r0, uint32_t& r1, uint32_t addr) {
    asm volatile("ldmatrix.sync.aligned.m8n8.x2.shared.b16 {%0,%1},[%2];\n"
                 : "=r"(r0), "=r"(r1) : "r"(addr));
}
__device__ __forceinline__ void mma16816(float* d, const uint32_t* a,
                                         uint32_t b0, uint32_t b1) {
    asm volatile(
        "mma.sync.aligned.m16n8k16.row.col.f32.bf16.bf16.f32 "
        "{%0,%1,%2,%3},{%4,%5,%6,%7},{%8,%9},{%0,%1,%2,%3};\n"
        : "+f"(d[0]), "+f"(d[1]), "+f"(d[2]), "+f"(d[3])
        : "r"(a[0]), "r"(a[1]), "r"(a[2]), "r"(a[3]), "r"(b0), "r"(b1));
}
__device__ __forceinline__ void cp16(void* s, const void* g) {
    asm volatile("cp.async.cg.shared.global [%0],[%1],16;\n"
                 :: "r"(smem_u32(s)), "l"(g));
}
__device__ __forceinline__ void cp_commit() {
    asm volatile("cp.async.commit_group;\n");
}
__device__ __forceinline__ float sigf(float x) { return 1.f / (1.f + __expf(-x)); }
__device__ __forceinline__ float tanhfast(float x) {
    return 2.f / (1.f + __expf(-2.f * x)) - 1.f;
}

// ------------------------------- prep X ------------------------------------
__global__ void k_prep_x(const float* __restrict__ x) {
    size_t stride = (size_t)gridDim.x * blockDim.x;
    for (size_t i = (size_t)blockIdx.x * blockDim.x + threadIdx.x;
         i < (size_t)MTOT * 512; i += stride) {
        size_t m = i >> 9, k = i & 511;
        float v = x[i];
        __nv_bfloat16 hi = __float2bfloat16(v);
        float r = v - __bfloat162float(hi);
        g_Ax[m * 1024 + k] = hi;
        g_Ax[m * 1024 + 512 + k] = __float2bfloat16(r);
    }
}

// ------------------------------- prep W ------------------------------------
__global__ void k_prep_w(const float* __restrict__ Wf, const float* __restrict__ bf,
                         const float* __restrict__ Wi, const float* __restrict__ bi,
                         const float* __restrict__ Wg, const float* __restrict__ bg,
                         const float* __restrict__ Wo, const float* __restrict__ bo,
                         const float* __restrict__ Rf, const float* __restrict__ Ri,
                         const float* __restrict__ Rg, const float* __restrict__ Ro) {
    int n = blockIdx.x;          // permuted column 0..2047
    int g = n & 3, hc = n >> 2;
    const float* W = (g == 0) ? Wf : (g == 1) ? Wi : (g == 2) ? Wg : Wo;
    const float* R = (g == 0) ? Rf : (g == 1) ? Ri : (g == 2) ? Rg : Ro;
    const float* bb = (g == 0) ? bf : (g == 1) ? bi : (g == 2) ? bg : bo;

    for (int k = threadIdx.x; k < 512; k += blockDim.x) {
        float wx = W[(size_t)k * 512 + hc];
        __nv_bfloat16 hi = __float2bfloat16(wx);
        g_Bx[(size_t)n * 1024 + k] = hi;
        g_Bx[(size_t)n * 1024 + 512 + k] =
            __float2bfloat16(wx - __bfloat162float(hi));

        float wh = W[(size_t)(512 + k) * 512 + hc] + R[(size_t)k * 512 + hc];
        __nv_bfloat16 hih = __float2bfloat16(wh);
        g_Br[(size_t)n * 1024 + k] = hih;
        g_Br[(size_t)n * 1024 + 512 + k] =
            __float2bfloat16(wh - __bfloat162float(hih));
    }
    if (threadIdx.x == 0) g_b4[n] = bb[hc];

    int gt = blockIdx.x * blockDim.x + threadIdx.x;
    if (gt < 2 * BB * 1024) g_hbuf[gt] = __float2bfloat16(0.f);  // h0 = 0
    if (gt < RNN_CTAS * 32) g_flags[gt] = 0;
}

// --------------------------- phase B: Z0 GEMM ------------------------------
// CTA tile 256x128, 16 warps (4m x 4n), warp tile 64x32. K chunks of 64, dbl buf.
#define P1_SA (256 * 72)
#define P1_SB (128 * 72)
#define P1_SMEM ((2 * P1_SA + 2 * P1_SB) * 2)

__global__ void __launch_bounds__(512, 1) k_gemm_x() {
    extern __shared__ __nv_bfloat16 smp[];
    __nv_bfloat16* sA = smp;                // [2][256*72]
    __nv_bfloat16* sB = smp + 2 * P1_SA;    // [2][128*72]
    const int m0 = blockIdx.x * 256, n0 = blockIdx.y * 128;
    const int tid = threadIdx.x, lane = tid & 31, w = tid >> 5;
    const int wm = w & 3, wn = w >> 2;      // 4 x 4
    const int tg = lane >> 2, t4 = lane & 3;

    float acc[4][4][4];
#pragma unroll
    for (int jt = 0; jt < 4; jt++) {
        int col = n0 + wn * 32 + jt * 8 + 2 * t4;
        float b0 = g_b4[col], b1 = g_b4[col + 1];
#pragma unroll
        for (int mt = 0; mt < 4; mt++) {
            acc[mt][jt][0] = b0; acc[mt][jt][1] = b1;
            acc[mt][jt][2] = b0; acc[mt][jt][3] = b1;
        }
    }

    auto issue = [&](int cc, int buf) {
        int seg = cc >> 3, kb = (cc & 7) * 64;
        int aoff = (seg == 1) ? 512 : 0, boff = (seg == 2) ? 512 : 0;
        size_t abase = (size_t)m0 * 1024 + aoff + kb;
#pragma unroll
        for (int u = tid; u < 2048; u += 512) {
            int r = u >> 3, c8 = (u & 7) * 8;
            cp16(&sA[buf * P1_SA + r * 72 + c8], &g_Ax[abase + (size_t)r * 1024 + c8]);
        }
        size_t bbase = (size_t)n0 * 1024 + boff + kb;
#pragma unroll
        for (int u = tid; u < 1024; u += 512) {
            int r = u >> 3, c8 = (u & 7) * 8;
            cp16(&sB[buf * P1_SB + r * 72 + c8], &g_Bx[bbase + (size_t)r * 1024 + c8]);
        }
        cp_commit();
    };

    issue(0, 0);
    for (int cc = 0; cc < 24; cc++) {
        int buf = cc & 1;
        if (cc < 23) {
            issue(cc + 1, buf ^ 1);
            asm volatile("cp.async.wait_group 1;\n");
        } else {
            asm volatile("cp.async.wait_group 0;\n");
        }
        __syncthreads();
#pragma unroll
        for (int kk = 0; kk < 4; kk++) {
            int ko = kk * 16;
            uint32_t a[4][4];
#pragma unroll
            for (int mt = 0; mt < 4; mt++) {
                int row = wm * 64 + mt * 16 + (lane & 15);
                int kx = ko + ((lane >> 4) << 3);
                ldsm_x4(a[mt][0], a[mt][1], a[mt][2], a[mt][3],
                        smem_u32(&sA[buf * P1_SA + row * 72 + kx]));
            }
#pragma unroll
            for (int jt = 0; jt < 4; jt++) {
                int nr = wn * 32 + jt * 8 + (lane & 7);
                int kx = ko + (((lane >> 3) & 1) << 3);
                uint32_t b0, b1;
                ldsm_x2(b0, b1, smem_u32(&sB[buf * P1_SB + nr * 72 + kx]));
#pragma unroll
                for (int mt = 0; mt < 4; mt++)
                    mma16816(acc[mt][jt], a[mt], b0, b1);
            }
        }
        __syncthreads();
    }

#pragma unroll
    for (int mt = 0; mt < 4; mt++) {
        int row = m0 + wm * 64 + mt * 16 + tg;
#pragma unroll
        for (int jt = 0; jt < 4; jt++) {
            int col = n0 + wn * 32 + jt * 8 + 2 * t4;
            *(float2*)&g_Z0[(size_t)row * 2048 + col] =
                make_float2(acc[mt][jt][0], acc[mt][jt][1]);
            *(float2*)&g_Z0[(size_t)(row + 8) * 2048 + col] =
                make_float2(acc[mt][jt][2], acc[mt][jt][3]);
        }
    }
}

// --------------------------- phase C: recurrence ---------------------------
// 128 CTAs = 4 groups (g = j>>5, 16 batch rows) x 32 slices (s = j&31, 64 cols).
// 8 warps = 4 N16-groups (nh) x 2 K-halves (kw). Warp: M16 x N16 x K768,
// 4 acc chains ([jt][kk&1]). Symmetric tail: warp owns tile jto=kw.
// R13: hi/lo chunked gather (GEMM starts after hi), pairwise named-barrier
// partial exchange (bar.sync nh+1, 64).
#define ST2 1032
#define P2_WB (64 * ST2)               // weights: 64 cols x 1024 (+pad)
#define P2_AB (16 * ST2)               // one h buffer: 16 rows
// floats after bf16 arrays: sZ 2048, sP 1024, sH 256, sC 256
#define P2_SMEM ((P2_WB + 2 * P2_AB) * 2 + (2048 + 1024 + 256 + 256) * 4)
#define HX_OFF ((size_t)TT * BB * HH)

__global__ void __launch_bounds__(256) k_rnn(float* __restrict__ out, int out_size) {
    extern __shared__ __nv_bfloat16 smp[];
    __nv_bfloat16* sB = smp;                         // [64][ST2]
    __nv_bfloat16* sA = smp + P2_WB;                 // [2][16][ST2]
    float* sZ = (float*)(smp + P2_WB + 2 * P2_AB);   // [2][16*64]
    float* sP = sZ + 2048;                           // [2][4][32][4] partials
    float* sH = sP + 1024;                           // [16 rows][16 hid]
    float* sC = sH + 256;                            // [16 rows][16 hid] (t=511)
    const int j = blockIdx.x, g = j >> 5, s = j & 31;
    const int r0 = g * 16;            // batch row base
    const int n0c = s * 64;           // permuted col base
    const int tid = threadIdx.x, lane = tid & 31, w = tid >> 5;
    const int nh = w & 3;             // N16 group: local cols [16nh, 16nh+16)
    const int kw = w >> 2;            // K half 0/1 = owned jt tile
    const int tg = lane >> 2, t4 = lane & 3;
    const bool ev = (t4 & 1) == 0;

    // resident weight slice (64 cols x 1024) for all 512 steps
    for (int u = tid; u < 64 * 128; u += 256) {
        int r = u >> 7, c8 = (u & 127) * 8;
        *(uint4*)&sB[r * ST2 + c8] = *(const uint4*)&g_Br[(size_t)(n0c + r) * 1024 + c8];
    }
    // prologue: Z(0) -> sZ[0]
    {
        int r = tid >> 4, c4 = (tid & 15) * 4;
        cp16(&sZ[r * 64 + c4], &g_Z0[(size_t)(r0 + r) * 2048 + n0c + c4]);
    }
    cp_commit();                       // pending: [Z(0)]

    const int arow = lane & 15;
    const int asel = (lane >> 4) << 3;
    const int brow4 = 16 * nh + ((lane >> 4) << 3) + (lane & 7);  // R3-verified
    const int bsel4 = ((lane >> 3) & 1) << 3;
    const unsigned* fp = &g_flags[(g * 32 + lane) * 32];   // lane 0..31

    const int jto = kw;               // owned jt tile of this warp
    float cst[2] = {0.f, 0.f};        // cell state rows of owned tile

    for (int t = 0; t < 512; t++) {
        int buf = t & 1, nb = buf ^ 1;

        // ---- group-local poll: lane waits CTA (g*32+lane)'s flag >= t ----
        {
            unsigned v;
            do {
                asm volatile("ld.acquire.gpu.global.u32 %0,[%1];" : "=r"(v) : "l"(fp));
            } while (v < (unsigned)t);
        }
        __syncwarp();

        // ---- H(t) hi chunk: 16 rows x 512 cols (16 KB) ----
#pragma unroll
        for (int i = 0; i < 4; i++) {
            int flat = i * 256 + tid;            // 0..1023
            int r = flat >> 6, c8 = (flat & 63) * 8;
            cp16(&sA[buf * P2_AB + r * ST2 + c8],
                 &g_hbuf[buf * 65536 + (r0 + r) * 1024 + c8]);
        }
        cp_commit();                   // group Hhi(t)
        // ---- H(t) lo chunk ----
#pragma unroll
        for (int i = 0; i < 4; i++) {
            int flat = i * 256 + tid;
            int r = flat >> 6, c8 = (flat & 63) * 8;
            cp16(&sA[buf * P2_AB + r * ST2 + 512 + c8],
                 &g_hbuf[buf * 65536 + (r0 + r) * 1024 + 512 + c8]);
        }
        cp_commit();                   // group Hlo(t)
        // ---- Z(t+1) prefetch (recurrence-independent) ----
        {
            int tz = (t + 1) & 511;
            int r = tid >> 4, c4 = (tid & 15) * 4;
            cp16(&sZ[nb * 1024 + r * 64 + c4],
                 &g_Z0[((size_t)tz * 64 + r0 + r) * 2048 + n0c + c4]);
        }
        cp_commit();                   // group Z(t+1)

        // pending [Z(t), Hhi, Hlo, Z(t+1)] -> wait 2: Z(t)+Hhi done.
        asm volatile("cp.async.wait_group 2;\n");
        __syncthreads();               // S1a (cross-thread visibility)

        // acc[jt][chain][e]: chain0 of the OWNED tile takes Z; rest zero
        float acc[2][2][4];
#pragma unroll
        for (int jt = 0; jt < 2; jt++)
#pragma unroll
            for (int c = 0; c < 2; c++)
#pragma unroll
                for (int e = 0; e < 4; e++) acc[jt][c][e] = 0.f;
        {
            int lc = 16 * nh + 8 * jto + 2 * t4;
            float2 v0 = *(float2*)&sZ[buf * 1024 + tg * 64 + lc];
            float2 v1 = *(float2*)&sZ[buf * 1024 + (tg + 8) * 64 + lc];
            acc[jto][0][0] = v0.x; acc[jto][0][1] = v0.y;
            acc[jto][0][2] = v1.x; acc[jto][0][3] = v1.y;
        }

        // GEMM segments on hi A data (seg aoff=0): hi*hi and hi*lo
        auto seg = [&](int aoff, int boff) {
#pragma unroll
            for (int kk = 0; kk < 16; kk++) {
                int ko = kw * 256 + kk * 16;
                uint32_t a[4], b[4];
                ldsm_x4(a[0], a[1], a[2], a[3],
                        smem_u32(&sA[buf * P2_AB + arow * ST2 + aoff + ko + asel]));
                ldsm_x4(b[0], b[1], b[2], b[3],
                        smem_u32(&sB[brow4 * ST2 + boff + ko + bsel4]));
                mma16816(acc[0][kk & 1], a, b[0], b[1]);
                mma16816(acc[1][kk & 1], a, b[2], b[3]);
            }
        };
        seg(0, 0);      // hi*hi
        seg(0, 512);    // hi*lo

        // pending [Hlo, Z(t+1)] -> wait 1: Hlo done.
        asm volatile("cp.async.wait_group 1;\n");
        __syncthreads();               // S1b
        seg(512, 0);    // lo*hi

        // ---- symmetric exchange: publish NON-owned tile's partial ----
        {
            int jno = jto ^ 1;
            float4 p = make_float4(acc[jno][0][0] + acc[jno][1][0],
                                   acc[jno][0][1] + acc[jno][1][1],
                                   acc[jno][0][2] + acc[jno][1][2],
                                   acc[jno][0][3] + acc[jno][1][3]);
            *(float4*)&sP[((kw * 4 + nh) * 32 + lane) * 4] = p;
        }
        // pairwise named barrier: warps (0,nh) and (1,nh) = 64 threads
        asm volatile("bar.sync %0, 64;\n" :: "r"(nh + 1) : "memory");

        // ---- reduce + gates for the OWNED tile (all 8 warps) ----
        {
            float4 p = *(float4*)&sP[(((kw ^ 1) * 4 + nh) * 32 + lane) * 4];
            float accF[4];
            accF[0] = acc[jto][0][0] + acc[jto][1][0] + p.x;
            accF[1] = acc[jto][0][1] + acc[jto][1][1] + p.y;
            accF[2] = acc[jto][0][2] + acc[jto][1][2] + p.z;
            accF[3] = acc[jto][0][3] + acc[jto][1][3] + p.w;

            float q0 = __shfl_xor_sync(0xffffffffu, accF[0], 1);
            float q1 = __shfl_xor_sync(0xffffffffu, accF[1], 1);
            float q2 = __shfl_xor_sync(0xffffffffu, accF[2], 1);
            float q3 = __shfl_xor_sync(0xffffffffu, accF[3], 1);
            float zf0 = ev ? accF[0] : q0, zi0 = ev ? accF[1] : q1;
            float zg0 = ev ? q0 : accF[0], zo0 = ev ? q1 : accF[1];
            float zf1 = ev ? accF[2] : q2, zi1 = ev ? accF[3] : q3;
            float zg1 = ev ? q2 : accF[2], zo1 = ev ? q3 : accF[3];

            float c0 = sigf(zf0) * cst[0] + sigf(zi0) * tanhfast(zg0);
            float c1 = sigf(zf1) * cst[1] + sigf(zi1) * tanhfast(zg1);
            cst[0] = c0; cst[1] = c1;
            float h0 = sigf(zo0) * tanhfast(c0);
            float h1 = sigf(zo1) * tanhfast(c1);

            if (ev) {
                int hcl = 4 * nh + 2 * jto + (t4 >> 1);   // local hidden 0..15
                sH[tg * 16 + hcl] = h0;
                sH[(tg + 8) * 16 + hcl] = h1;
                if (t == 511) {
                    sC[tg * 16 + hcl] = c0;
                    sC[(tg + 8) * 16 + hcl] = c1;
                }
            }
        }
        __syncthreads();               // S2: sH complete

        // ---- coalesced hbuf writes (hi half by tid<128, lo by tid>=128) ----
        {
            int half = tid >> 7;
            int u = tid & 127;
            int row = u >> 3, c2 = (u & 7) * 2;
            float f0 = sH[row * 16 + c2], f1 = sH[row * 16 + c2 + 1];
            __nv_bfloat16 b0 = __float2bfloat16(f0);
            __nv_bfloat16 b1 = __float2bfloat16(f1);
            __nv_bfloat162 pr;
            if (half == 0) { pr.x = b0; pr.y = b1; }
            else {
                pr.x = __float2bfloat16(f0 - __bfloat162float(b0));
                pr.y = __float2bfloat16(f1 - __bfloat162float(b1));
            }
            *(__nv_bfloat162*)&g_hbuf[nb * 65536 + (r0 + row) * 1024
                                      + half * 512 + 16 * s + c2] = pr;
        }
        __syncthreads();               // S3: hbuf stores issued by all threads

        // publish h_{t+1}: release store (ordered after S3 via happens-before)
        if (tid == 0) {
            asm volatile("st.release.gpu.global.u32 [%0],%1;"
                         :: "l"(&g_flags[j * 32]), "r"((unsigned)(t + 1)));
        }

        // ---- fp32 outputs AFTER the flag (no in-kernel consumer) ----
        {
            int row = tid >> 4, c = tid & 15;
            out[((size_t)t * 64 + r0 + row) * 512 + 16 * s + c] = sH[row * 16 + c];
        }
        if (t == 511) {
            int row = tid >> 4, c = tid & 15;
            size_t o1 = HX_OFF + (size_t)(r0 + row) * 512 + 16 * s + c;
            if (HX_OFF + 32768 <= (size_t)out_size) out[o1] = sH[row * 16 + c];
            if (HX_OFF + 65536 <= (size_t)out_size) out[o1 + 32768] = sC[row * 16 + c];
        }
    }
}

// ------------------------------- launch ------------------------------------
extern "C" void kernel_launch(void* const* d_in, const int* in_sizes, int n_in,
                              void* d_out, int out_size) {
    const float* x  = (const float*)d_in[0];
    const float* Wf = (const float*)d_in[1];
    const float* bf = (const float*)d_in[2];
    const float* Wi = (const float*)d_in[3];
    const float* bi = (const float*)d_in[4];
    const float* Wg = (const float*)d_in[5];
    const float* bg = (const float*)d_in[6];
    const float* Wo = (const float*)d_in[7];
    const float* bo = (const float*)d_in[8];
    const float* Rf = (const float*)d_in[9];
    const float* Ri = (const float*)d_in[10];
    const float* Rg = (const float*)d_in[11];
    const float* Ro = (const float*)d_in[12];

    cudaFuncSetAttribute(k_gemm_x, cudaFuncAttributeMaxDynamicSharedMemorySize, P1_SMEM);
    cudaFuncSetAttribute(k_rnn, cudaFuncAttributeMaxDynamicSharedMemorySize, P2_SMEM);

    k_prep_x<<<4096, 256>>>(x);
    k_prep_w<<<2048, 256>>>(Wf, bf, Wi, bi, Wg, bg, Wo, bo, Rf, Ri, Rg, Ro);
    k_gemm_x<<<dim3(128, 16), 512, P1_SMEM>>>();
    k_rnn<<<RNN_CTAS, 256, P2_SMEM>>>((float*)d_out, out_size);
}

// round 16
// speedup vs baseline: 1.0371x; 1.0371x over previous
#include <cuda_runtime.h>
#include <cuda_bf16.h>
#include <cstdint>
#include <cstddef>

// ---------------------------------------------------------------------------
// QLSTM  T=512 B=64 D=512 H=512
//  z_t = x_t@Wx + b4 + h_t@(Wh+R)
//  Phase A (prep):   split X and weights into bf16 hi/lo, permute columns
//  Phase B (gemm):   Z0[32768,2048] = X@Wx + b4   (3-product bf16 split)
//                    R14: K-chunks of 128 (12 iters, half the barriers)
//  Phase C (rnn):    EXACT R12 (measured best, 2.53 ms): 128 CTAs =
//                    4 batch-groups x 32 N-slices; symmetric tail split.
//  (R15 = R14 resubmitted unchanged; R14 bench was an infra failure.)
//  Column permutation: z column for (hidden hc, gate g) stored at n = hc*4+g
// ---------------------------------------------------------------------------

#define TT 512
#define BB 64
#define DD 512
#define HH 512
#define NCOLS 2048
#define MTOT (TT * BB)          // 32768
#define RNN_CTAS 128

// ------------------------- static device scratch ---------------------------
__device__ __align__(128) __nv_bfloat16 g_Ax[(size_t)MTOT * 1024];   // X split  [m][hi|lo]
__device__ __align__(128) __nv_bfloat16 g_Bx[(size_t)NCOLS * 1024];  // Wx split [n][hi|lo]
__device__ __align__(128) __nv_bfloat16 g_Br[(size_t)NCOLS * 1024];  // (Wh+R)   [n][hi|lo]
__device__ __align__(128) float g_b4[NCOLS];
__device__ __align__(128) float g_Z0[(size_t)MTOT * NCOLS];          // 256 MB
__device__ __align__(128) __nv_bfloat16 g_hbuf[2 * BB * 1024];       // h split ping-pong
__device__ __align__(128) unsigned g_flags[RNN_CTAS * 32];           // 1 line / CTA

// ------------------------------ helpers ------------------------------------
__device__ __forceinline__ uint32_t smem_u32(const void* p) {
    return (uint32_t)__cvta_generic_to_shared(p);
}
__device__ __forceinline__ void ldsm_x4(uint32_t& r0, uint32_t& r1, uint32_t& r2,
                                        uint32_t& r3, uint32_t addr) {
    asm volatile("ldmatrix.sync.aligned.m8n8.x4.shared.b16 {%0,%1,%2,%3},[%4];\n"
                 : "=r"(r0), "=r"(r1), "=r"(r2), "=r"(r3) : "r"(addr));
}
__device__ __forceinline__ void ldsm_x2(uint32_t& r0, uint32_t& r1, uint32_t addr) {
    asm volatile("ldmatrix.sync.aligned.m8n8.x2.shared.b16 {%0,%1},[%2];\n"
                 : "=r"(r0), "=r"(r1) : "r"(addr));
}
__device__ __forceinline__ void mma16816(float* d, const uint32_t* a,
                                         uint32_t b0, uint32_t b1) {
    asm volatile(
        "mma.sync.aligned.m16n8k16.row.col.f32.bf16.bf16.f32 "
        "{%0,%1,%2,%3},{%4,%5,%6,%7},{%8,%9},{%0,%1,%2,%3};\n"
        : "+f"(d[0]), "+f"(d[1]), "+f"(d[2]), "+f"(d[3])
        : "r"(a[0]), "r"(a[1]), "r"(a[2]), "r"(a[3]), "r"(b0), "r"(b1));
}
__device__ __forceinline__ void cp16(void* s, const void* g) {
    asm volatile("cp.async.cg.shared.global [%0],[%1],16;\n"
                 :: "r"(smem_u32(s)), "l"(g));
}
__device__ __forceinline__ void cp_commit() {
    asm volatile("cp.async.commit_group;\n");
}
__device__ __forceinline__ float sigf(float x) { return 1.f / (1.f + __expf(-x)); }
__device__ __forceinline__ float tanhfast(float x) {
    return 2.f / (1.f + __expf(-2.f * x)) - 1.f;
}

// ------------------------------- prep X ------------------------------------
__global__ void k_prep_x(const float* __restrict__ x) {
    size_t stride = (size_t)gridDim.x * blockDim.x;
    for (size_t i = (size_t)blockIdx.x * blockDim.x + threadIdx.x;
         i < (size_t)MTOT * 512; i += stride) {
        size_t m = i >> 9, k = i & 511;
        float v = x[i];
        __nv_bfloat16 hi = __float2bfloat16(v);
        float r = v - __bfloat162float(hi);
        g_Ax[m * 1024 + k] = hi;
        g_Ax[m * 1024 + 512 + k] = __float2bfloat16(r);
    }
}

// ------------------------------- prep W ------------------------------------
__global__ void k_prep_w(const float* __restrict__ Wf, const float* __restrict__ bf,
                         const float* __restrict__ Wi, const float* __restrict__ bi,
                         const float* __restrict__ Wg, const float* __restrict__ bg,
                         const float* __restrict__ Wo, const float* __restrict__ bo,
                         const float* __restrict__ Rf, const float* __restrict__ Ri,
                         const float* __restrict__ Rg, const float* __restrict__ Ro) {
    int n = blockIdx.x;          // permuted column 0..2047
    int g = n & 3, hc = n >> 2;
    const float* W = (g == 0) ? Wf : (g == 1) ? Wi : (g == 2) ? Wg : Wo;
    const float* R = (g == 0) ? Rf : (g == 1) ? Ri : (g == 2) ? Rg : Ro;
    const float* bb = (g == 0) ? bf : (g == 1) ? bi : (g == 2) ? bg : bo;

    for (int k = threadIdx.x; k < 512; k += blockDim.x) {
        float wx = W[(size_t)k * 512 + hc];
        __nv_bfloat16 hi = __float2bfloat16(wx);
        g_Bx[(size_t)n * 1024 + k] = hi;
        g_Bx[(size_t)n * 1024 + 512 + k] =
            __float2bfloat16(wx - __bfloat162float(hi));

        float wh = W[(size_t)(512 + k) * 512 + hc] + R[(size_t)k * 512 + hc];
        __nv_bfloat16 hih = __float2bfloat16(wh);
        g_Br[(size_t)n * 1024 + k] = hih;
        g_Br[(size_t)n * 1024 + 512 + k] =
            __float2bfloat16(wh - __bfloat162float(hih));
    }
    if (threadIdx.x == 0) g_b4[n] = bb[hc];

    int gt = blockIdx.x * blockDim.x + threadIdx.x;
    if (gt < 2 * BB * 1024) g_hbuf[gt] = __float2bfloat16(0.f);  // h0 = 0
    if (gt < RNN_CTAS * 32) g_flags[gt] = 0;
}

// --------------------------- phase B: Z0 GEMM ------------------------------
// CTA tile 256x128, 16 warps (4m x 4n), warp tile 64x32. K chunks of 128
// (12 iterations), double-buffered. Stride 136 elem keeps ldsm conflict-free.
#define STB 136
#define P1_SA (256 * STB)
#define P1_SB (128 * STB)
#define P1_SMEM ((2 * P1_SA + 2 * P1_SB) * 2)

__global__ void __launch_bounds__(512, 1) k_gemm_x() {
    extern __shared__ __nv_bfloat16 smp[];
    __nv_bfloat16* sA = smp;                // [2][256*STB]
    __nv_bfloat16* sB = smp + 2 * P1_SA;    // [2][128*STB]
    const int m0 = blockIdx.x * 256, n0 = blockIdx.y * 128;
    const int tid = threadIdx.x, lane = tid & 31, w = tid >> 5;
    const int wm = w & 3, wn = w >> 2;      // 4 x 4
    const int tg = lane >> 2, t4 = lane & 3;

    float acc[4][4][4];
#pragma unroll
    for (int jt = 0; jt < 4; jt++) {
        int col = n0 + wn * 32 + jt * 8 + 2 * t4;
        float b0 = g_b4[col], b1 = g_b4[col + 1];
#pragma unroll
        for (int mt = 0; mt < 4; mt++) {
            acc[mt][jt][0] = b0; acc[mt][jt][1] = b1;
            acc[mt][jt][2] = b0; acc[mt][jt][3] = b1;
        }
    }

    auto issue = [&](int cc, int buf) {
        int seg = cc >> 2, kb = (cc & 3) * 128;
        int aoff = (seg == 1) ? 512 : 0, boff = (seg == 2) ? 512 : 0;
        size_t abase = (size_t)m0 * 1024 + aoff + kb;
#pragma unroll
        for (int u = tid; u < 4096; u += 512) {
            int r = u >> 4, c8 = (u & 15) * 8;
            cp16(&sA[buf * P1_SA + r * STB + c8], &g_Ax[abase + (size_t)r * 1024 + c8]);
        }
        size_t bbase = (size_t)n0 * 1024 + boff + kb;
#pragma unroll
        for (int u = tid; u < 2048; u += 512) {
            int r = u >> 4, c8 = (u & 15) * 8;
            cp16(&sB[buf * P1_SB + r * STB + c8], &g_Bx[bbase + (size_t)r * 1024 + c8]);
        }
        cp_commit();
    };

    issue(0, 0);
    for (int cc = 0; cc < 12; cc++) {
        int buf = cc & 1;
        if (cc < 11) {
            issue(cc + 1, buf ^ 1);
            asm volatile("cp.async.wait_group 1;\n");
        } else {
            asm volatile("cp.async.wait_group 0;\n");
        }
        __syncthreads();
#pragma unroll
        for (int kk = 0; kk < 8; kk++) {
            int ko = kk * 16;
            uint32_t a[4][4];
#pragma unroll
            for (int mt = 0; mt < 4; mt++) {
                int row = wm * 64 + mt * 16 + (lane & 15);
                int kx = ko + ((lane >> 4) << 3);
                ldsm_x4(a[mt][0], a[mt][1], a[mt][2], a[mt][3],
                        smem_u32(&sA[buf * P1_SA + row * STB + kx]));
            }
#pragma unroll
            for (int jt = 0; jt < 4; jt++) {
                int nr = wn * 32 + jt * 8 + (lane & 7);
                int kx = ko + (((lane >> 3) & 1) << 3);
                uint32_t b0, b1;
                ldsm_x2(b0, b1, smem_u32(&sB[buf * P1_SB + nr * STB + kx]));
#pragma unroll
                for (int mt = 0; mt < 4; mt++)
                    mma16816(acc[mt][jt], a[mt], b0, b1);
            }
        }
        __syncthreads();
    }

#pragma unroll
    for (int mt = 0; mt < 4; mt++) {
        int row = m0 + wm * 64 + mt * 16 + tg;
#pragma unroll
        for (int jt = 0; jt < 4; jt++) {
            int col = n0 + wn * 32 + jt * 8 + 2 * t4;
            *(float2*)&g_Z0[(size_t)row * 2048 + col] =
                make_float2(acc[mt][jt][0], acc[mt][jt][1]);
            *(float2*)&g_Z0[(size_t)(row + 8) * 2048 + col] =
                make_float2(acc[mt][jt][2], acc[mt][jt][3]);
        }
    }
}

// --------------------------- phase C: recurrence ---------------------------
// EXACT R12 (measured best). 128 CTAs = 4 groups x 32 slices.
// 8 warps = 4 N16-groups (nh) x 2 K-halves (kw). Warp: M16 x N16 x K768,
// symmetric tail: warp owns tile jto=kw (Z-init, reduction, gates).
#define ST2 1032
#define P2_WB (64 * ST2)               // weights: 64 cols x 1024 (+pad)
#define P2_AB (16 * ST2)               // one h buffer: 16 rows
#define P2_SMEM ((P2_WB + 2 * P2_AB) * 2 + (2048 + 1024 + 256 + 256) * 4)
#define HX_OFF ((size_t)TT * BB * HH)

__global__ void __launch_bounds__(256) k_rnn(float* __restrict__ out, int out_size) {
    extern __shared__ __nv_bfloat16 smp[];
    __nv_bfloat16* sB = smp;                         // [64][ST2]
    __nv_bfloat16* sA = smp + P2_WB;                 // [2][16][ST2]
    float* sZ = (float*)(smp + P2_WB + 2 * P2_AB);   // [2][16*64]
    float* sP = sZ + 2048;                           // [2][4][32][4] partials
    float* sH = sP + 1024;                           // [16 rows][16 hid]
    float* sC = sH + 256;                            // [16 rows][16 hid] (t=511)
    const int j = blockIdx.x, g = j >> 5, s = j & 31;
    const int r0 = g * 16;            // batch row base
    const int n0c = s * 64;           // permuted col base
    const int tid = threadIdx.x, lane = tid & 31, w = tid >> 5;
    const int nh = w & 3;             // N16 group: local cols [16nh, 16nh+16)
    const int kw = w >> 2;            // K half 0/1 = owned jt tile
    const int tg = lane >> 2, t4 = lane & 3;
    const bool ev = (t4 & 1) == 0;

    // resident weight slice (64 cols x 1024) for all 512 steps
    for (int u = tid; u < 64 * 128; u += 256) {
        int r = u >> 7, c8 = (u & 127) * 8;
        *(uint4*)&sB[r * ST2 + c8] = *(const uint4*)&g_Br[(size_t)(n0c + r) * 1024 + c8];
    }
    // prologue: Z(0) -> sZ[0]
    {
        int r = tid >> 4, c4 = (tid & 15) * 4;
        cp16(&sZ[r * 64 + c4], &g_Z0[(size_t)(r0 + r) * 2048 + n0c + c4]);
    }
    cp_commit();                       // pending: [Z(0)]

    const int arow = lane & 15;
    const int asel = (lane >> 4) << 3;
    const int brow4 = 16 * nh + ((lane >> 4) << 3) + (lane & 7);  // R3-verified
    const int bsel4 = ((lane >> 3) & 1) << 3;
    const unsigned* fp = &g_flags[(g * 32 + lane) * 32];   // lane 0..31

    const int jto = kw;               // owned jt tile of this warp
    float cst[2] = {0.f, 0.f};        // cell state rows of owned tile

    for (int t = 0; t < 512; t++) {
        int buf = t & 1, nb = buf ^ 1;

        // ---- group-local poll: lane waits CTA (g*32+lane)'s flag >= t ----
        {
            unsigned v;
            do {
                asm volatile("ld.acquire.gpu.global.u32 %0,[%1];" : "=r"(v) : "l"(fp));
            } while (v < (unsigned)t);
        }
        __syncwarp();

        // ---- H(t): own-group h rows (16 x 1024 bf16 = 32 KB) ----
#pragma unroll
        for (int i = 0; i < 8; i++) {
            int flat = i * 256 + tid;            // 0..2047
            int r = flat >> 7, c8 = (flat & 127) * 8;
            cp16(&sA[buf * P2_AB + r * ST2 + c8],
                 &g_hbuf[buf * 65536 + (r0 + r) * 1024 + c8]);
        }
        cp_commit();                   // group H(t)
        // ---- Z(t+1) prefetch (recurrence-independent) ----
        {
            int tz = (t + 1) & 511;
            int r = tid >> 4, c4 = (tid & 15) * 4;
            cp16(&sZ[nb * 1024 + r * 64 + c4],
                 &g_Z0[((size_t)tz * 64 + r0 + r) * 2048 + n0c + c4]);
        }
        cp_commit();                   // group Z(t+1)

        // complete Z(t)+H(t) (Z(t+1) stays in flight), then CTA barrier so
        // ALL threads' cp.async data is visible (wait_group is per-thread).
        asm volatile("cp.async.wait_group 1;\n");
        __syncthreads();               // S1

        // acc[jt][chain][e]: chain0 of the OWNED tile takes Z; rest zero
        float acc[2][2][4];
#pragma unroll
        for (int jt = 0; jt < 2; jt++)
#pragma unroll
            for (int c = 0; c < 2; c++)
#pragma unroll
                for (int e = 0; e < 4; e++) acc[jt][c][e] = 0.f;
        {
            int lc = 16 * nh + 8 * jto + 2 * t4;
            float2 v0 = *(float2*)&sZ[buf * 1024 + tg * 64 + lc];
            float2 v1 = *(float2*)&sZ[buf * 1024 + (tg + 8) * 64 + lc];
            acc[jto][0][0] = v0.x; acc[jto][0][1] = v0.y;
            acc[jto][0][2] = v1.x; acc[jto][0][3] = v1.y;
        }

        // ---- GEMM: warp = cols [16nh,16nh+16), K-half kw of each 512-seg ----
#pragma unroll
        for (int seg = 0; seg < 3; seg++) {
            int aoff = (seg == 1) ? 512 : 0, boff = (seg == 2) ? 512 : 0;
#pragma unroll
            for (int kk = 0; kk < 16; kk++) {
                int ko = kw * 256 + kk * 16;
                uint32_t a[4], b[4];
                ldsm_x4(a[0], a[1], a[2], a[3],
                        smem_u32(&sA[buf * P2_AB + arow * ST2 + aoff + ko + asel]));
                ldsm_x4(b[0], b[1], b[2], b[3],
                        smem_u32(&sB[brow4 * ST2 + boff + ko + bsel4]));
                mma16816(acc[0][kk & 1], a, b[0], b[1]);
                mma16816(acc[1][kk & 1], a, b[2], b[3]);
            }
        }

        // ---- symmetric exchange: publish NON-owned tile's partial ----
        {
            int jno = jto ^ 1;
            float4 p = make_float4(acc[jno][0][0] + acc[jno][1][0],
                                   acc[jno][0][1] + acc[jno][1][1],
                                   acc[jno][0][2] + acc[jno][1][2],
                                   acc[jno][0][3] + acc[jno][1][3]);
            *(float4*)&sP[((kw * 4 + nh) * 32 + lane) * 4] = p;
        }
        __syncthreads();               // S_red

        // ---- reduce + gates for the OWNED tile (all 8 warps) ----
        {
            float4 p = *(float4*)&sP[(((kw ^ 1) * 4 + nh) * 32 + lane) * 4];
            float accF[4];
            accF[0] = acc[jto][0][0] + acc[jto][1][0] + p.x;
            accF[1] = acc[jto][0][1] + acc[jto][1][1] + p.y;
            accF[2] = acc[jto][0][2] + acc[jto][1][2] + p.z;
            accF[3] = acc[jto][0][3] + acc[jto][1][3] + p.w;

            float q0 = __shfl_xor_sync(0xffffffffu, accF[0], 1);
            float q1 = __shfl_xor_sync(0xffffffffu, accF[1], 1);
            float q2 = __shfl_xor_sync(0xffffffffu, accF[2], 1);
            float q3 = __shfl_xor_sync(0xffffffffu, accF[3], 1);
            float zf0 = ev ? accF[0] : q0, zi0 = ev ? accF[1] : q1;
            float zg0 = ev ? q0 : accF[0], zo0 = ev ? q1 : accF[1];
            float zf1 = ev ? accF[2] : q2, zi1 = ev ? accF[3] : q3;
            float zg1 = ev ? q2 : accF[2], zo1 = ev ? q3 : accF[3];

            float c0 = sigf(zf0) * cst[0] + sigf(zi0) * tanhfast(zg0);
            float c1 = sigf(zf1) * cst[1] + sigf(zi1) * tanhfast(zg1);
            cst[0] = c0; cst[1] = c1;
            float h0 = sigf(zo0) * tanhfast(c0);
            float h1 = sigf(zo1) * tanhfast(c1);

            if (ev) {
                int hcl = 4 * nh + 2 * jto + (t4 >> 1);   // local hidden 0..15
                sH[tg * 16 + hcl] = h0;
                sH[(tg + 8) * 16 + hcl] = h1;
                if (t == 511) {
                    sC[tg * 16 + hcl] = c0;
                    sC[(tg + 8) * 16 + hcl] = c1;
                }
            }
        }
        __syncthreads();               // S2: sH complete

        // ---- coalesced hbuf writes (hi half by tid<128, lo by tid>=128) ----
        {
            int half = tid >> 7;
            int u = tid & 127;
            int row = u >> 3, c2 = (u & 7) * 2;
            float f0 = sH[row * 16 + c2], f1 = sH[row * 16 + c2 + 1];
            __nv_bfloat16 b0 = __float2bfloat16(f0);
            __nv_bfloat16 b1 = __float2bfloat16(f1);
            __nv_bfloat162 pr;
            if (half == 0) { pr.x = b0; pr.y = b1; }
            else {
                pr.x = __float2bfloat16(f0 - __bfloat162float(b0));
                pr.y = __float2bfloat16(f1 - __bfloat162float(b1));
            }
            *(__nv_bfloat162*)&g_hbuf[nb * 65536 + (r0 + row) * 1024
                                      + half * 512 + 16 * s + c2] = pr;
        }
        __syncthreads();               // S3: hbuf stores issued by all threads

        // publish h_{t+1}: release store (ordered after S3 via happens-before)
        if (tid == 0) {
            asm volatile("st.release.gpu.global.u32 [%0],%1;"
                         :: "l"(&g_flags[j * 32]), "r"((unsigned)(t + 1)));
        }

        // ---- fp32 outputs AFTER the flag (no in-kernel consumer) ----
        {
            int row = tid >> 4, c = tid & 15;
            out[((size_t)t * 64 + r0 + row) * 512 + 16 * s + c] = sH[row * 16 + c];
        }
        if (t == 511) {
            int row = tid >> 4, c = tid & 15;
            size_t o1 = HX_OFF + (size_t)(r0 + row) * 512 + 16 * s + c;
            if (HX_OFF + 32768 <= (size_t)out_size) out[o1] = sH[row * 16 + c];
            if (HX_OFF + 65536 <= (size_t)out_size) out[o1 + 32768] = sC[row * 16 + c];
        }
    }
}

// ------------------------------- launch ------------------------------------
extern "C" void kernel_launch(void* const* d_in, const int* in_sizes, int n_in,
                              void* d_out, int out_size) {
    const float* x  = (const float*)d_in[0];
    const float* Wf = (const float*)d_in[1];
    const float* bf = (const float*)d_in[2];
    const float* Wi = (const float*)d_in[3];
    const float* bi = (const float*)d_in[4];
    const float* Wg = (const float*)d_in[5];
    const float* bg = (const float*)d_in[6];
    const float* Wo = (const float*)d_in[7];
    const float* bo = (const float*)d_in[8];
    const float* Rf = (const float*)d_in[9];
    const float* Ri = (const float*)d_in[10];
    const float* Rg = (const float*)d_in[11];
    const float* Ro = (const float*)d_in[12];

    cudaFuncSetAttribute(k_gemm_x, cudaFuncAttributeMaxDynamicSharedMemorySize, P1_SMEM);
    cudaFuncSetAttribute(k_rnn, cudaFuncAttributeMaxDynamicSharedMemorySize, P2_SMEM);

    k_prep_x<<<4096, 256>>>(x);
    k_prep_w<<<2048, 256>>>(Wf, bf, Wi, bi, Wg, bg, Wo, bo, Rf, Ri, Rg, Ro);
    k_gemm_x<<<dim3(128, 16), 512, P1_SMEM>>>();
    k_rnn<<<RNN_CTAS, 256, P2_SMEM>>>((float*)d_out, out_size);
}